// round 13
// baseline (speedup 1.0000x reference)
#include <cuda_runtime.h>
#include <math_constants.h>

// ChamferDistance: x (8,8192,3) f32, y (8,8192,3) f32 -> scalar f32.
// FMA-pipe bound brute force with packed fma.rn.f32x2 (FFMA2).
//   d^2(q,r) = qq + (rr - 2*dot(q,r)); queries pre-scaled by -2.
//   min(sqrt(v+EPS)) == sqrt(min(v)+EPS) -> one sqrt per point at the end.
// R13: NO smem, NO barriers in the hot loop. Refs are pre-interleaved+splatted
// into a 2MB gmem array by a prep kernel; the pass loop is 2 broadcast LDG.128
// (L1-resident, 8KB/block) + 24 FFMA2 + 8 fused mins per j-iter. Results go
// through atomicMin on int-viewed floats (v >= 0), killing the 16MB
// g_minpart round-trip (reduce now reads 512KB).

#define BATCH   8
#define NPTS    8192
#define RSPLIT  32
#define TPB     128
#define U       8                              // queries per thread
#define QPB     (TPB * U)                      // 1024 queries per block
#define QBLK    (NPTS / QPB)                   // 8
#define RCHUNK  (NPTS / RSPLIT)                // 256 refs -> 128 pairs per block
#define NPAIRS  (RCHUNK / 2)                   // 128
#define EPS_F   1e-10f
#define POS_INF_BITS 0x7F800000

// Interleaved pair-splatted refs: [dir][b][pair][8] = x0,x1,y0,y1,z0,z1,rr0,rr1
__device__ float g_refint[2][BATCH][NPTS * 4];
__device__ int   g_min[2][BATCH * NPTS];
__device__ float g_partial[16];

__device__ __forceinline__ unsigned long long f2_fma(unsigned long long a, unsigned long long b, unsigned long long c) {
    unsigned long long d;
    asm("fma.rn.f32x2 %0, %1, %2, %3;" : "=l"(d) : "l"(a), "l"(b), "l"(c));
    return d;
}
__device__ __forceinline__ unsigned long long f2_pack(float a, float b) {
    unsigned long long r;
    asm("mov.b64 %0, {%1, %2};" : "=l"(r) : "f"(a), "f"(b));
    return r;
}
__device__ __forceinline__ void f2_unpack(unsigned long long v, float& lo, float& hi) {
    asm("mov.b64 {%0, %1}, %2;" : "=f"(lo), "=f"(hi) : "l"(v));
}

// One thread per (dir, b, pair): 2*8*4096 = 65536 threads. Also inits g_min.
__global__ __launch_bounds__(256)
void chamfer_prep_kernel(const float* __restrict__ x, const float* __restrict__ y) {
    const int tid  = blockIdx.x * 256 + threadIdx.x;       // 0..65535
    const int pair = tid & 4095;
    const int b    = (tid >> 12) & 7;
    const int dir  = tid >> 15;
    const float* __restrict__ src = dir ? x : y;           // refs for this dir

    const float* p = src + ((size_t)b * NPTS + 2 * pair) * 3;
    float x0 = p[0], y0 = p[1], z0 = p[2];
    float x1 = p[3], y1 = p[4], z1 = p[5];
    float rr0 = x0 * x0 + y0 * y0 + z0 * z0;
    float rr1 = x1 * x1 + y1 * y1 + z1 * z1;

    float4* d = reinterpret_cast<float4*>(&g_refint[dir][b][pair * 8]);
    d[0] = make_float4(x0, x1, y0, y1);
    d[1] = make_float4(z0, z1, rr0, rr1);

    // Init two g_min entries per thread (131072 total).
    ((int*)g_min)[2 * tid]     = POS_INF_BITS;
    ((int*)g_min)[2 * tid + 1] = POS_INF_BITS;
}

// grid: (QBLK=8, RSPLIT=32, 16) where z = dir*8 + b. No smem, no barriers.
__global__ __launch_bounds__(TPB, 7)
void chamfer_pass_kernel(const float* __restrict__ x, const float* __restrict__ y) {
    const int dir = blockIdx.z >> 3;
    const int b   = blockIdx.z & 7;
    const float* __restrict__ Q = dir ? y : x;   // query side

    const int t = threadIdx.x;

    float minv[U];
    unsigned long long qx2[U], qy2[U], qz2[U];   // query coords pre-scaled by -2, splatted
    {
        const float* qp = Q + ((size_t)b * NPTS + blockIdx.x * QPB + t) * 3;
#pragma unroll
        for (int u = 0; u < U; u++) {
            float a = qp[0] * -2.0f, c = qp[1] * -2.0f, e = qp[2] * -2.0f;
            qx2[u] = f2_pack(a, a);
            qy2[u] = f2_pack(c, c);
            qz2[u] = f2_pack(e, e);
            minv[u] = CUDART_INF_F;
            qp += TPB * 3;
        }
    }

    // 128 ref pairs for this chunk, pre-splatted; broadcast LDG.128 x2 per pair.
    const ulonglong2* __restrict__ base =
        reinterpret_cast<const ulonglong2*>(&g_refint[dir][b][blockIdx.y * (NPAIRS * 8)]);

#pragma unroll 4
    for (int j = 0; j < NPAIRS; j++) {
        ulonglong2 A  = base[2 * j];       // {x-pair, y-pair}
        ulonglong2 Bv = base[2 * j + 1];   // {z-pair, rr-pair}
#pragma unroll
        for (int u = 0; u < U; u++) {
            unsigned long long acc = f2_fma(qx2[u], A.x, Bv.y);  // rr - 2 qx rx
            acc = f2_fma(qy2[u], A.y, acc);
            acc = f2_fma(qz2[u], Bv.x, acc);                     // rr - 2 dot (packed x2)
            float lo, hi;
            f2_unpack(acc, lo, hi);
            minv[u] = fminf(minv[u], fminf(lo, hi));
        }
    }

    // Add qq (reloaded; L1-hot) and fold into global mins via int atomicMin
    // (v >= 0 up to ~1e-7 rounding; int ordering == float ordering here).
    {
        const int qidx0 = b * NPTS + blockIdx.x * QPB + t;
        const float* qp = Q + (size_t)qidx0 * 3;
#pragma unroll
        for (int u = 0; u < U; u++) {
            float qq = qp[0] * qp[0] + qp[1] * qp[1] + qp[2] * qp[2];
            atomicMin(&g_min[dir][qidx0 + u * TPB], __float_as_int(minv[u] + qq));
            qp += TPB * 3;
        }
    }
}

// 16 blocks: dir(2) x batch(8). Sum sqrt(min + EPS) over the 8192 queries.
__global__ __launch_bounds__(256)
void chamfer_reduce_kernel() {
    const int dir = blockIdx.x >> 3;
    const int b   = blockIdx.x & 7;
    const int t   = threadIdx.x;
    const int* __restrict__ arr = &g_min[dir][b * NPTS];

    float s = 0.0f;
#pragma unroll 4
    for (int n = t; n < NPTS; n += 256)
        s += sqrtf(__int_as_float(arr[n]) + EPS_F);

    __shared__ float red[256];
    red[t] = s;
    __syncthreads();
    for (int o = 128; o > 0; o >>= 1) {
        if (t < o) red[t] += red[t + o];
        __syncthreads();
    }
    if (t == 0) g_partial[blockIdx.x] = red[0];
}

__global__ __launch_bounds__(32)
void chamfer_final_kernel(float* __restrict__ out) {
    if (threadIdx.x == 0) {
        float s = 0.0f;
#pragma unroll
        for (int b = 0; b < BATCH; b++)
            s += fmaxf(g_partial[b], g_partial[8 + b]) * (1.0f / (float)NPTS);
        *out = s;
    }
}

extern "C" void kernel_launch(void* const* d_in, const int* in_sizes, int n_in,
                              void* d_out, int out_size) {
    const float* x = (const float*)d_in[0];
    const float* y = (const float*)d_in[1];
    float* out = (float*)d_out;

    chamfer_prep_kernel<<<256, 256>>>(x, y);
    dim3 grid(QBLK, RSPLIT, 16);                 // 8 x 32 x 16 = 4096 blocks
    chamfer_pass_kernel<<<grid, TPB>>>(x, y);
    chamfer_reduce_kernel<<<16, 256>>>();
    chamfer_final_kernel<<<1, 32>>>(out);
}

// round 15
// speedup vs baseline: 1.1434x; 1.1434x over previous
#include <cuda_runtime.h>
#include <math_constants.h>

// ChamferDistance: x (8,8192,3) f32, y (8,8192,3) f32 -> scalar f32.
// FMA-pipe bound brute force with packed fma.rn.f32x2 (FFMA2).
//   d^2(q,r) = qq + (rr - 2*dot(q,r)); queries pre-scaled by -2; qq added in reduce.
//   min(sqrt(v+EPS)) == sqrt(min(v)+EPS) -> one sqrt per point at the end.
// R14: R12 champion hot loop (U=8, LDS broadcast, 7 blocks/SM) with
//  - TR=256=RCHUNK: whole chunk staged once -> ZERO barriers around the j-loop
//  - 2 kernels total: reduce uses last-block-does-final (ticket + fence),
//    saving ~8us of tiny-kernel graph-replay overhead.

#define BATCH   8
#define NPTS    8192
#define RSPLIT  32
#define TPB     128
#define U       8                              // queries per thread
#define QPB     (TPB * U)                      // 1024 queries per block
#define QBLK    (NPTS / QPB)                   // 8
#define RCHUNK  (NPTS / RSPLIT)                // 256 refs per block (one stage)
#define EPS_F   1e-10f

__device__ float g_minpart[2][RSPLIT][BATCH * NPTS];
__device__ float g_partial[128];
__device__ int   g_ticket;                     // self-resetting completion counter

__device__ __forceinline__ unsigned long long f2_fma(unsigned long long a, unsigned long long b, unsigned long long c) {
    unsigned long long d;
    asm("fma.rn.f32x2 %0, %1, %2, %3;" : "=l"(d) : "l"(a), "l"(b), "l"(c));
    return d;
}
__device__ __forceinline__ unsigned long long f2_pack(float a, float b) {
    unsigned long long r;
    asm("mov.b64 %0, {%1, %2};" : "=l"(r) : "f"(a), "f"(b));
    return r;
}
__device__ __forceinline__ void f2_unpack(unsigned long long v, float& lo, float& hi) {
    asm("mov.b64 {%0, %1}, %2;" : "=f"(lo), "=f"(hi) : "l"(v));
}

// grid: (QBLK=8, RSPLIT=32, 16) where z = dir*8 + b
__global__ __launch_bounds__(TPB, 7)
void chamfer_pass_kernel(const float* __restrict__ x, const float* __restrict__ y) {
    const int dir = blockIdx.z >> 3;
    const int b   = blockIdx.z & 7;
    const float* __restrict__ Q = dir ? y : x;   // query side
    const float* __restrict__ R = dir ? x : y;   // reference side

    const int t = threadIdx.x;

    // Pair-interleaved chunk (256 refs = 128 pairs), staged ONCE per block:
    //   sm[8j+0..1]=x pair, [8j+2..3]=y pair, [8j+4..5]=z pair, [8j+6..7]=rr pair
    __shared__ float sm[RCHUNK * 4];

    // Stage: each thread loads 2 ref points (t and t+128).
    {
        const float* rp = R + ((size_t)b * NPTS + blockIdx.y * RCHUNK + t) * 3;
#pragma unroll
        for (int h = 0; h < 2; h++) {
            float rx = rp[0], ry = rp[1], rz = rp[2];
            const int idx = t + h * TPB;
            const int jj  = (idx >> 1) * 8 + (idx & 1);
            sm[jj + 0] = rx;
            sm[jj + 2] = ry;
            sm[jj + 4] = rz;
            sm[jj + 6] = rx * rx + ry * ry + rz * rz;
            rp += TPB * 3;
        }
    }

    float minv[U];
    unsigned long long qx2[U], qy2[U], qz2[U];   // query coords pre-scaled by -2, splatted
    {
        const float* qp = Q + ((size_t)b * NPTS + blockIdx.x * QPB + t) * 3;
#pragma unroll
        for (int u = 0; u < U; u++) {
            float a = qp[0] * -2.0f, c = qp[1] * -2.0f, e = qp[2] * -2.0f;
            qx2[u] = f2_pack(a, a);
            qy2[u] = f2_pack(c, c);
            qz2[u] = f2_pack(e, e);
            minv[u] = CUDART_INF_F;
            qp += TPB * 3;
        }
    }
    __syncthreads();   // the ONLY barrier: staged chunk visible

#pragma unroll 4
    for (int j = 0; j < RCHUNK / 2; j++) {
        // Two LDS.128 -> four pre-packed f32x2 operands (broadcast, conflict-free),
        // each pair reused by 8 queries.
        ulonglong2 A  = *reinterpret_cast<const ulonglong2*>(&sm[8 * j]);      // {x-pair, y-pair}
        ulonglong2 Bv = *reinterpret_cast<const ulonglong2*>(&sm[8 * j + 4]);  // {z-pair, rr-pair}
#pragma unroll
        for (int u = 0; u < U; u++) {
            unsigned long long acc = f2_fma(qx2[u], A.x, Bv.y);  // rr - 2 qx rx
            acc = f2_fma(qy2[u], A.y, acc);
            acc = f2_fma(qz2[u], Bv.x, acc);                     // rr - 2 dot (packed x2)
            float lo, hi;
            f2_unpack(acc, lo, hi);
            minv[u] = fminf(minv[u], fminf(lo, hi));
        }
    }

    float* outp = &g_minpart[dir][blockIdx.y][b * NPTS + blockIdx.x * QPB + t];
#pragma unroll
    for (int u = 0; u < U; u++) {
        outp[u * TPB] = minv[u];
    }
}

// 128 blocks: dir(2) x batch(8) x chunk(8); each covers 1024 queries.
// Adds the deferred qq term before the sqrt. Last block performs the final
// combine (ticket pattern; ticket self-resets for graph-replay determinism).
__global__ __launch_bounds__(256)
void chamfer_reduce_kernel(const float* __restrict__ x, const float* __restrict__ y,
                           float* __restrict__ out) {
    const int dir   = blockIdx.x >> 6;
    const int b     = (blockIdx.x >> 3) & 7;
    const int chunk = blockIdx.x & 7;
    const int t     = threadIdx.x;
    const float* __restrict__ Qside = dir ? y : x;

    float s = 0.0f;
#pragma unroll
    for (int k = 0; k < 4; k++) {
        const int q = b * NPTS + chunk * 1024 + k * 256 + t;
        float v = g_minpart[dir][0][q];
#pragma unroll
        for (int r = 1; r < RSPLIT; r++) v = fminf(v, g_minpart[dir][r][q]);
        const float* p = Qside + (size_t)q * 3;
        float qq = p[0] * p[0] + p[1] * p[1] + p[2] * p[2];
        s += sqrtf(v + qq + EPS_F);
    }

    __shared__ float red[256];
    red[t] = s;
    __syncthreads();
    for (int o = 128; o > 0; o >>= 1) {
        if (t < o) red[t] += red[t + o];
        __syncthreads();
    }

    __shared__ bool amLast;
    if (t == 0) {
        g_partial[blockIdx.x] = red[0];
        __threadfence();
        amLast = (atomicAdd(&g_ticket, 1) == 127);
    }
    __syncthreads();

    if (amLast) {
        // 128 partials: lane t<16 sums its 8 chunks; thread 0 combines.
        float ps = 0.0f;
        if (t < 16) {
#pragma unroll
            for (int c = 0; c < 8; c++) ps += g_partial[t * 8 + c];
            red[t] = ps;
        }
        __syncthreads();
        if (t == 0) {
            float s2 = 0.0f;
#pragma unroll
            for (int bb = 0; bb < BATCH; bb++)
                s2 += fmaxf(red[bb], red[8 + bb]) * (1.0f / (float)NPTS);
            *out = s2;
            g_ticket = 0;          // reset for next graph replay (deterministic)
        }
    }
}

extern "C" void kernel_launch(void* const* d_in, const int* in_sizes, int n_in,
                              void* d_out, int out_size) {
    const float* x = (const float*)d_in[0];
    const float* y = (const float*)d_in[1];
    float* out = (float*)d_out;

    dim3 grid(QBLK, RSPLIT, 16);                 // 8 x 32 x 16 = 4096 blocks
    chamfer_pass_kernel<<<grid, TPB>>>(x, y);
    chamfer_reduce_kernel<<<128, 256>>>(x, y, out);
}